// round 2
// baseline (speedup 1.0000x reference)
#include <cuda_runtime.h>

// Problem constants
#define NPATCH   32768      // 128 batch * 16*16 patches
#define DDIM     256        // 16 channels * 4*4 patch
#define KCODES   1024
// 1/(2*variance) where variance = -(256 / (2*ln 0.1))  =>  inv2var = ln(10)/256
#define INV2VAR  0.0089944730195076785f
#define SMOOTH_R 64         // weight at |d|=64 is exp(-36.8) ~ 1e-16: negligible

// Scratch (static device globals; no allocation at runtime)
__device__ float g_patch[NPATCH * DDIM];     // 33.5 MB patchified x
__device__ float g_xnorm[NPATCH];
__device__ float g_cnorm[KCODES];
__device__ float g_smooth[KCODES * DDIM];    // Gaussian-smoothed codebook
__device__ int   g_bmu[NPATCH];

// ---------------------------------------------------------------------------
// K0: patchify  (N,C,H,W) -> (i, d) with i = n*256 + ph*16 + pw, d = c*16+py*4+px
// ---------------------------------------------------------------------------
__global__ void k_patchify(const float* __restrict__ x) {
    int idx = blockIdx.x * blockDim.x + threadIdx.x;
    int d   = idx & 255;
    int i   = idx >> 8;
    int n   = i >> 8;
    int rem = i & 255;
    int ph = rem >> 4, pw = rem & 15;
    int c = d >> 4, py = (d >> 2) & 3, px = d & 3;
    int src = ((n * 16 + c) * 64 + ph * 4 + py) * 64 + pw * 4 + px;
    g_patch[idx] = x[src];
}

// ---------------------------------------------------------------------------
// K0b: per-patch squared norms (one warp per row)
// ---------------------------------------------------------------------------
__global__ void k_xnorm() {
    int row  = blockIdx.x * 8 + (threadIdx.x >> 5);
    int lane = threadIdx.x & 31;
    const float* p = g_patch + row * DDIM;
    float s = 0.0f;
    #pragma unroll
    for (int j = 0; j < DDIM / 32; ++j) {
        float v = p[lane + j * 32];
        s = fmaf(v, v, s);
    }
    #pragma unroll
    for (int o = 16; o; o >>= 1) s += __shfl_xor_sync(0xffffffffu, s, o);
    if (lane == 0) g_xnorm[row] = s;
}

// ---------------------------------------------------------------------------
// K1a: per-code squared norms
// ---------------------------------------------------------------------------
__global__ void k_cnorm(const float* __restrict__ cb) {
    int row  = blockIdx.x * 8 + (threadIdx.x >> 5);
    int lane = threadIdx.x & 31;
    const float* p = cb + row * DDIM;
    float s = 0.0f;
    #pragma unroll
    for (int j = 0; j < DDIM / 32; ++j) {
        float v = p[lane + j * 32];
        s = fmaf(v, v, s);
    }
    #pragma unroll
    for (int o = 16; o; o >>= 1) s += __shfl_xor_sync(0xffffffffu, s, o);
    if (lane == 0) g_cnorm[row] = s;
}

// ---------------------------------------------------------------------------
// K1b: Gaussian-smoothed codebook.
// Block handles 16 consecutive output rows j; thread handles one dim d.
// smoothed[j][d] = sum_k exp(-(k-j)^2 * INV2VAR) * cb[k][d], radius SMOOTH_R.
// ---------------------------------------------------------------------------
__global__ void k_smooth(const float* __restrict__ cb) {
    __shared__ float wtab[160];   // delta in [-80, 79] -> index delta+80
    int jbase = blockIdx.x * 16;
    int tid = threadIdx.x;
    if (tid < 160) {
        float dd = (float)(tid - 80);
        wtab[tid] = expf(-(dd * dd) * INV2VAR);
    }
    __syncthreads();

    float acc[16];
    #pragma unroll
    for (int t = 0; t < 16; ++t) acc[t] = 0.0f;

    int klo = jbase - SMOOTH_R;
    int khi = jbase + 15 + SMOOTH_R;      // inclusive
    if (klo < 0) klo = 0;
    if (khi > KCODES - 1) khi = KCODES - 1;

    for (int kk = klo; kk <= khi; ++kk) {
        float v = cb[kk * DDIM + tid];
        int base = kk - jbase + 80;       // in [16, 159]
        #pragma unroll
        for (int t = 0; t < 16; ++t)
            acc[t] = fmaf(wtab[base - t], v, acc[t]);
    }
    #pragma unroll
    for (int t = 0; t < 16; ++t)
        g_smooth[(jbase + t) * DDIM + tid] = acc[t];
}

// ---------------------------------------------------------------------------
// K2: fused distance GEMM + argmin.
// Block: 128 patches x 128-code chunks (x8 chunks), 256 threads, 8x8 tiles.
// d2 = fl( fl(xnorm - 2*s) + cnorm ), argmin with first-index tie-break,
// mirroring the reference's fp32 rounding chain.
// ---------------------------------------------------------------------------
__launch_bounds__(256, 2)
__global__ void k_argmin(const float* __restrict__ cb) {
    __shared__ float Xs[8][128];
    __shared__ float Cs[8][128];
    __shared__ float xn_sh[128];
    __shared__ float cn_sh[128];
    __shared__ float bestv[128];
    __shared__ int   besti[128];

    int tid = threadIdx.x;
    int m0  = blockIdx.x * 128;
    int tr  = tid >> 4;        // 0..15 : row group (8 rows each)
    int tc  = tid & 15;        // 0..15 : col group (8 cols each)
    int mrow = tid >> 1;       // 0..127 : load row
    int q    = tid & 1;        // which half of the 8-dim slab

    if (tid < 128) {
        xn_sh[tid] = g_xnorm[m0 + tid];
        bestv[tid] = __int_as_float(0x7f800000);  // +inf
        besti[tid] = 0x7fffffff;
    }

    for (int nch = 0; nch < 8; ++nch) {
        __syncthreads();   // protects cn_sh / bestv across chunk boundary
        int n0 = nch << 7;
        if (tid < 128) cn_sh[tid] = g_cnorm[n0 + tid];

        float acc[64];
        #pragma unroll
        for (int z = 0; z < 64; ++z) acc[z] = 0.0f;

        for (int d0 = 0; d0 < DDIM; d0 += 8) {
            __syncthreads();
            float4 xa = *(const float4*)&g_patch[(m0 + mrow) * DDIM + d0 + q * 4];
            float4 ca = *(const float4*)&cb[(n0 + mrow) * DDIM + d0 + q * 4];
            Xs[q * 4 + 0][mrow] = xa.x; Xs[q * 4 + 1][mrow] = xa.y;
            Xs[q * 4 + 2][mrow] = xa.z; Xs[q * 4 + 3][mrow] = xa.w;
            Cs[q * 4 + 0][mrow] = ca.x; Cs[q * 4 + 1][mrow] = ca.y;
            Cs[q * 4 + 2][mrow] = ca.z; Cs[q * 4 + 3][mrow] = ca.w;
            __syncthreads();

            #pragma unroll
            for (int kk = 0; kk < 8; ++kk) {
                float a[8], b[8];
                float4 t0 = *(const float4*)&Xs[kk][tr * 8];
                float4 t1 = *(const float4*)&Xs[kk][tr * 8 + 4];
                a[0]=t0.x; a[1]=t0.y; a[2]=t0.z; a[3]=t0.w;
                a[4]=t1.x; a[5]=t1.y; a[6]=t1.z; a[7]=t1.w;
                float4 u0 = *(const float4*)&Cs[kk][tc * 8];
                float4 u1 = *(const float4*)&Cs[kk][tc * 8 + 4];
                b[0]=u0.x; b[1]=u0.y; b[2]=u0.z; b[3]=u0.w;
                b[4]=u1.x; b[5]=u1.y; b[6]=u1.z; b[7]=u1.w;
                #pragma unroll
                for (int r = 0; r < 8; ++r)
                    #pragma unroll
                    for (int j = 0; j < 8; ++j)
                        acc[r * 8 + j] = fmaf(a[r], b[j], acc[r * 8 + j]);
            }
        }

        // Epilogue: d2 + argmin reduce
        #pragma unroll
        for (int r = 0; r < 8; ++r) {
            float xnr = xn_sh[tr * 8 + r];
            float bv = __int_as_float(0x7f800000);
            int   bi = 0x7fffffff;
            #pragma unroll
            for (int j = 0; j < 8; ++j) {
                int code = n0 + tc * 8 + j;
                // fl( fl(xn - 2*s) + cn )  — identical rounding to reference
                float t = __fmaf_rn(-2.0f, acc[r * 8 + j], xnr);
                float v = __fadd_rn(t, cn_sh[tc * 8 + j]);
                if (v < bv || (v == bv && code < bi)) { bv = v; bi = code; }
            }
            // reduce across the 16 threads sharing this row (width-16 segments)
            #pragma unroll
            for (int o = 1; o < 16; o <<= 1) {
                float ov = __shfl_xor_sync(0xffffffffu, bv, o, 16);
                int   oi = __shfl_xor_sync(0xffffffffu, bi, o, 16);
                if (ov < bv || (ov == bv && oi < bi)) { bv = ov; bi = oi; }
            }
            if (tc == 0) {
                int row = tr * 8 + r;
                if (bv < bestv[row] || (bv == bestv[row] && bi < besti[row])) {
                    bestv[row] = bv; besti[row] = bi;
                }
            }
        }
    }
    __syncthreads();
    if (tid < 128) g_bmu[m0 + tid] = besti[tid];
}

// ---------------------------------------------------------------------------
// K3: gather smoothed[bmu] and un-patchify directly into the output layout
// ---------------------------------------------------------------------------
__global__ void k_output(float* __restrict__ out) {
    int idx = blockIdx.x * blockDim.x + threadIdx.x;
    int w = idx & 63;
    int h = (idx >> 6) & 63;
    int c = (idx >> 12) & 15;
    int n = idx >> 16;
    int i = (n << 8) + ((h >> 2) << 4) + (w >> 2);
    int d = (c << 4) + ((h & 3) << 2) + (w & 3);
    out[idx] = g_smooth[g_bmu[i] * DDIM + d];
}

// ---------------------------------------------------------------------------
extern "C" void kernel_launch(void* const* d_in, const int* in_sizes, int n_in,
                              void* d_out, int out_size) {
    const float* x  = (const float*)d_in[0];   // (128,16,64,64)
    const float* cb = (const float*)d_in[1];   // (1024,256)
    float* out = (float*)d_out;

    k_patchify<<<NPATCH * DDIM / 256, 256>>>(x);
    k_xnorm  <<<NPATCH / 8, 256>>>();
    k_cnorm  <<<KCODES / 8, 256>>>(cb);
    k_smooth <<<KCODES / 16, 256>>>(cb);
    k_argmin <<<NPATCH / 128, 256>>>(cb);
    k_output <<<NPATCH * DDIM / 256, 256>>>(out);
}